// round 2
// baseline (speedup 1.0000x reference)
#include <cuda_runtime.h>
#include <math.h>

#define H 128
#define B 2048
#define S 64
#define PRED 50
#define BT 16            // batch rows per block
#define NBLK (B / BT)    // 128 blocks
#define NTHR 256

// ---------------- transposed-weight scratch (device globals: no allocs) ----------------
__device__ float g_wt_l0[132 * 512];   // rows 0..3 = wih0^T, rows 4..131 = whh0^T
__device__ float g_wt_l1[256 * 512];   // rows 0..127 = wih1^T, 128..255 = whh1^T
__device__ float g_b_l0[512];
__device__ float g_b_l1[512];
__device__ float g_wt_gi0[128 * 384];
__device__ float g_wt_gh0[128 * 384];
__device__ float g_wt_gi1[128 * 384];
__device__ float g_wt_gh1[128 * 384];
__device__ float g_wt_br[128 * 128];
__device__ float g_wt_fc1[128 * 64];

// ---------------- weight pre-transpose (k-major for coalesced GEMM loads) ----------------
__global__ void prep_kernel(
    const float* __restrict__ lwih0, const float* __restrict__ lwhh0,
    const float* __restrict__ lbih0, const float* __restrict__ lbhh0,
    const float* __restrict__ lwih1, const float* __restrict__ lwhh1,
    const float* __restrict__ lbih1, const float* __restrict__ lbhh1,
    const float* __restrict__ gwi0, const float* __restrict__ gwh0,
    const float* __restrict__ gwi1, const float* __restrict__ gwh1,
    const float* __restrict__ brw, const float* __restrict__ fc1w)
{
    int i0 = blockIdx.x * blockDim.x + threadIdx.x;
    int stride = gridDim.x * blockDim.x;
    for (int i = i0; i < 132 * 512; i += stride) {
        int k = i / 512, c = i % 512;
        g_wt_l0[i] = (k < 4) ? lwih0[c * 4 + k] : lwhh0[c * 128 + (k - 4)];
    }
    for (int i = i0; i < 256 * 512; i += stride) {
        int k = i / 512, c = i % 512;
        g_wt_l1[i] = (k < 128) ? lwih1[c * 128 + k] : lwhh1[c * 128 + (k - 128)];
    }
    for (int i = i0; i < 512; i += stride) {
        g_b_l0[i] = lbih0[i] + lbhh0[i];
        g_b_l1[i] = lbih1[i] + lbhh1[i];
    }
    for (int i = i0; i < 128 * 384; i += stride) {
        int k = i / 384, c = i % 384;
        g_wt_gi0[i] = gwi0[c * 128 + k];
        g_wt_gh0[i] = gwh0[c * 128 + k];
        g_wt_gi1[i] = gwi1[c * 128 + k];
        g_wt_gh1[i] = gwh1[c * 128 + k];
    }
    for (int i = i0; i < 128 * 128; i += stride) {
        int k = i >> 7, c = i & 127;
        g_wt_br[i] = brw[c * 128 + k];
    }
    for (int i = i0; i < 128 * 64; i += stride) {
        int k = i / 64, c = i % 64;
        g_wt_fc1[i] = fc1w[c * 128 + k];
    }
}

// ---------------- block GEMM: out[16][C] = A[16][K] @ WT[K][C] + bias ----------------
// 256 threads: 2 row-groups of 8 rows x 128 col-groups of CPT cols.
// A in smem (warp-uniform broadcast LDS.128), WT in global (coalesced LDG).
template<int K, int C, int CPT, bool RELU = false>
__device__ __forceinline__ void gemm16(const float* __restrict__ A, int astr,
                                       const float* __restrict__ WT,
                                       const float* __restrict__ bias,
                                       float* __restrict__ outp, int ostr)
{
    const int tid = threadIdx.x;
    const int rbase = (tid >> 7) * 8;
    const int c0 = (tid & 127) * CPT;
    if (c0 >= C) return;

    float bj[CPT];
#pragma unroll
    for (int j = 0; j < CPT; j++) bj[j] = bias[c0 + j];

    float acc[8][CPT];
#pragma unroll
    for (int r = 0; r < 8; r++)
#pragma unroll
        for (int j = 0; j < CPT; j++) acc[r][j] = bj[j];

#pragma unroll 2
    for (int k = 0; k < K; k += 4) {
        float4 a[8];
#pragma unroll
        for (int r = 0; r < 8; r++)
            a[r] = *reinterpret_cast<const float4*>(A + (rbase + r) * astr + k);

        float w[4][CPT];
        if constexpr (CPT == 4) {
#pragma unroll
            for (int kk = 0; kk < 4; kk++) {
                float4 wv = *reinterpret_cast<const float4*>(WT + (k + kk) * C + c0);
                w[kk][0] = wv.x; w[kk][1] = wv.y; w[kk][2] = wv.z; w[kk][3] = wv.w;
            }
        } else {
#pragma unroll
            for (int kk = 0; kk < 4; kk++)
#pragma unroll
                for (int j = 0; j < CPT; j++)
                    w[kk][j] = WT[(k + kk) * C + c0 + j];
        }
#pragma unroll
        for (int r = 0; r < 8; r++) {
#pragma unroll
            for (int j = 0; j < CPT; j++) {
                acc[r][j] = fmaf(a[r].x, w[0][j], acc[r][j]);
                acc[r][j] = fmaf(a[r].y, w[1][j], acc[r][j]);
                acc[r][j] = fmaf(a[r].z, w[2][j], acc[r][j]);
                acc[r][j] = fmaf(a[r].w, w[3][j], acc[r][j]);
            }
        }
    }
#pragma unroll
    for (int r = 0; r < 8; r++) {
        if constexpr (CPT == 4) {
            float4 v;
            v.x = RELU ? fmaxf(acc[r][0], 0.f) : acc[r][0];
            v.y = RELU ? fmaxf(acc[r][1], 0.f) : acc[r][1];
            v.z = RELU ? fmaxf(acc[r][2], 0.f) : acc[r][2];
            v.w = RELU ? fmaxf(acc[r][3], 0.f) : acc[r][3];
            *reinterpret_cast<float4*>(outp + (rbase + r) * ostr + c0) = v;
        } else {
#pragma unroll
            for (int j = 0; j < CPT; j++)
                outp[(rbase + r) * ostr + c0 + j] =
                    RELU ? fmaxf(acc[r][j], 0.f) : acc[r][j];
        }
    }
}

__device__ __forceinline__ float sigm(float x) { return 1.0f / (1.0f + __expf(-x)); }

// gates g[16][gs] with PyTorch order i,f,g,o (chunks of 128); updates c; writes h to 1-2 dests
__device__ __forceinline__ void lstm_combine(const float* __restrict__ g, int gs,
                                             float* __restrict__ c,
                                             float* __restrict__ d1, int d1s,
                                             float* __restrict__ d2, int d2s)
{
    for (int idx = threadIdx.x; idx < BT * H; idx += NTHR) {
        int r = idx >> 7, j = idx & 127;
        const float* gr = g + r * gs;
        float ii = gr[j], ff = gr[H + j], gg = gr[2 * H + j], oo = gr[3 * H + j];
        float cc = sigm(ff) * c[idx] + sigm(ii) * tanhf(gg);
        c[idx] = cc;
        float h = sigm(oo) * tanhf(cc);
        d1[r * d1s + j] = h;
        if (d2) d2[r * d2s + j] = h;
    }
}

// gi/gh [16][384], PyTorch order r,z,n; updates hbuf in place
__device__ __forceinline__ void gru_combine(const float* __restrict__ gi,
                                            const float* __restrict__ gh,
                                            float* __restrict__ hbuf)
{
    for (int idx = threadIdx.x; idx < BT * H; idx += NTHR) {
        int r = idx >> 7, j = idx & 127;
        const float* gir = gi + r * 384;
        const float* ghr = gh + r * 384;
        float rr = sigm(gir[j] + ghr[j]);
        float zz = sigm(gir[H + j] + ghr[H + j]);
        float nn = tanhf(gir[2 * H + j] + rr * ghr[2 * H + j]);
        hbuf[idx] = (1.f - zz) * nn + zz * hbuf[idx];
    }
}

// ---------------- one persistent-style kernel: whole network per batch tile ----------------
__global__ void __launch_bounds__(NTHR, 1) rnn_kernel(
    const float* __restrict__ x,
    const float* __restrict__ gbi0, const float* __restrict__ gbh0,
    const float* __restrict__ gbi1, const float* __restrict__ gbh1,
    const float* __restrict__ brb, const float* __restrict__ fc1b,
    const float* __restrict__ fc2w, const float* __restrict__ fc2b,
    float* __restrict__ out)
{
    extern __shared__ float sm[];
    float* xh0 = sm;                  // [16][132]: cols 0..3 = x_t, 4..131 = h0
    float* xh1 = xh0 + BT * 132;      // [16][256]: cols 0..127 = h0_new, 128..255 = h1
    float* c0  = xh1 + BT * 256;      // [16][128]
    float* c1  = c0 + BT * H;         // [16][128]
    float* gbuf = c1 + BT * H;        // [16][768] scratch (LSTM gates / GRU gi+gh)
    float* hd0 = gbuf + BT * 768;     // [16][128]
    float* hd1 = hd0 + BT * H;        // [16][128]
    float* inp = hd1 + BT * H;        // [16][128]
    float* fcz = inp + BT * H;        // [16][64]

    const int tid = threadIdx.x;
    const int b0 = blockIdx.x * BT;

    for (int i = tid; i < BT * 132; i += NTHR) xh0[i] = 0.f;
    for (int i = tid; i < BT * 256; i += NTHR) xh1[i] = 0.f;
    for (int i = tid; i < BT * H; i += NTHR) { c0[i] = 0.f; c1[i] = 0.f; }
    __syncthreads();

    // ---------- LSTM encoder, both layers fused per timestep ----------
    for (int t = 0; t < S; t++) {
        if (tid < BT * 4) {
            int r = tid >> 2, k = tid & 3;
            xh0[r * 132 + k] = x[(size_t)(b0 + r) * S * 4 + t * 4 + k];
        }
        __syncthreads();
        gemm16<132, 512, 4>(xh0, 132, g_wt_l0, g_b_l0, gbuf, 512);
        __syncthreads();
        lstm_combine(gbuf, 512, c0, xh0 + 4, 132, xh1, 256);
        __syncthreads();
        gemm16<256, 512, 4>(xh1, 256, g_wt_l1, g_b_l1, gbuf, 512);
        __syncthreads();
        lstm_combine(gbuf, 512, c1, xh1 + 128, 256, nullptr, 0);
        __syncthreads();
    }

    // ---------- bridge: hg = tanh(h_n @ bridge^T + b) ----------
    gemm16<128, 128, 1>(xh0 + 4, 132, g_wt_br, brb, gbuf, 128);
    __syncthreads();
    for (int i = tid; i < BT * H; i += NTHR) hd0[i] = tanhf(gbuf[i]);
    __syncthreads();
    gemm16<128, 128, 1>(xh1 + 128, 256, g_wt_br, brb, gbuf, 128);
    __syncthreads();
    for (int i = tid; i < BT * H; i += NTHR) {
        hd1[i] = tanhf(gbuf[i]);
        int r = i >> 7, j = i & 127;
        inp[i] = xh1[r * 256 + 128 + j];   // dec_in0 = h_n[-1]
    }
    __syncthreads();

    float* gi = gbuf;
    float* gh = gbuf + BT * 384;

    // ---------- autoregressive GRU decode + MLP head ----------
    for (int t = 0; t < PRED; t++) {
        const float* Ain = (t == 0) ? inp : hd1;
        gemm16<128, 384, 3>(Ain, 128, g_wt_gi0, gbi0, gi, 384);
        gemm16<128, 384, 3>(hd0, 128, g_wt_gh0, gbh0, gh, 384);
        __syncthreads();
        gru_combine(gi, gh, hd0);
        __syncthreads();
        gemm16<128, 384, 3>(hd0, 128, g_wt_gi1, gbi1, gi, 384);
        gemm16<128, 384, 3>(hd1, 128, g_wt_gh1, gbh1, gh, 384);
        __syncthreads();
        gru_combine(gi, gh, hd1);
        __syncthreads();
        gemm16<128, 64, 1, true>(hd1, 128, g_wt_fc1, fc1b, fcz, 64);  // relu(fc1)
        __syncthreads();
        if (tid < 32) {   // fc2: 16 rows x 2 cols
            int r = tid >> 1, cc = tid & 1;
            float s = fc2b[cc];
#pragma unroll
            for (int k = 0; k < 64; k++) s = fmaf(fcz[r * 64 + k], fc2w[cc * 64 + k], s);
            out[(size_t)(b0 + r) * PRED * 2 + t * 2 + cc] = s;
        }
        __syncthreads();
    }
}

extern "C" void kernel_launch(void* const* d_in, const int* in_sizes, int n_in,
                              void* d_out, int out_size)
{
    // pred_len is the only size-1 input; its metadata position is ambiguous
    // (dict vs signature order) — skip it, the rest keep their relative order.
    const float* p[24];
    int np = 0;
    for (int i = 0; i < n_in && np < 24; i++) {
        if (in_sizes[i] == 1) continue;
        p[np++] = (const float*)d_in[i];
    }
    const float* x = p[0];
    const float *lwih0 = p[1], *lwhh0 = p[2], *lbih0 = p[3], *lbhh0 = p[4];
    const float *lwih1 = p[5], *lwhh1 = p[6], *lbih1 = p[7], *lbhh1 = p[8];
    const float *gwi0 = p[9], *gwh0 = p[10], *gbi0 = p[11], *gbh0 = p[12];
    const float *gwi1 = p[13], *gwh1 = p[14], *gbi1 = p[15], *gbh1 = p[16];
    const float *brw = p[17], *brb = p[18];
    const float *fc1w = p[19], *fc1b = p[20];
    const float *fc2w = p[21], *fc2b = p[22];

    prep_kernel<<<132, 256>>>(lwih0, lwhh0, lbih0, lbhh0, lwih1, lwhh1, lbih1, lbhh1,
                              gwi0, gwh0, gwi1, gwh1, brw, fc1w);

    const int smem = (BT * 132 + BT * 256 + BT * H * 2 + BT * 768 + BT * H * 3 + BT * 64)
                     * (int)sizeof(float);   // 119040 bytes
    cudaFuncSetAttribute(rnn_kernel, cudaFuncAttributeMaxDynamicSharedMemorySize, smem);
    rnn_kernel<<<NBLK, NTHR, smem>>>(x, gbi0, gbh0, gbi1, gbh1, brb, fc1b, fc2w, fc2b,
                                     (float*)d_out);
}

// round 3
// speedup vs baseline: 1.1416x; 1.1416x over previous
#include <cuda_runtime.h>
#include <math.h>

#define H 128
#define S 64
#define PRED 50
#define BT 16
#define NBLK 128
#define NTHR 512

// ---------- gate-interleaved transposed weights: [k][j*4+g] ----------
__device__ __align__(16) float g_wx0[4 * 512];      // wih0: k<4
__device__ __align__(16) float g_wh0[128 * 512];
__device__ __align__(16) float g_b0[512];           // bih0+bhh0, [j*4+g]
__device__ __align__(16) float g_wi1[128 * 512];
__device__ __align__(16) float g_wh1[128 * 512];
__device__ __align__(16) float g_b1[512];
__device__ __align__(16) float g_wgi0[128 * 512];   // GRU: gate 3 padded 0
__device__ __align__(16) float g_wgh0[128 * 512];
__device__ __align__(16) float g_wgi1[128 * 512];
__device__ __align__(16) float g_wgh1[128 * 512];
__device__ __align__(16) float g_bgi0[512];
__device__ __align__(16) float g_bgh0[512];
__device__ __align__(16) float g_bgi1[512];
__device__ __align__(16) float g_bgh1[512];
__device__ __align__(16) float g_wbr[128 * 128];    // [k][j]
__device__ __align__(16) float g_wfc1[128 * 64];    // [k][c]

__global__ void prep_kernel(
    const float* __restrict__ lwih0, const float* __restrict__ lwhh0,
    const float* __restrict__ lbih0, const float* __restrict__ lbhh0,
    const float* __restrict__ lwih1, const float* __restrict__ lwhh1,
    const float* __restrict__ lbih1, const float* __restrict__ lbhh1,
    const float* __restrict__ gwi0, const float* __restrict__ gwh0,
    const float* __restrict__ gbi0, const float* __restrict__ gbh0,
    const float* __restrict__ gwi1, const float* __restrict__ gwh1,
    const float* __restrict__ gbi1, const float* __restrict__ gbh1,
    const float* __restrict__ brw, const float* __restrict__ fc1w)
{
    int i0 = blockIdx.x * blockDim.x + threadIdx.x;
    int st = gridDim.x * blockDim.x;
    for (int i = i0; i < 4 * 512; i += st) {
        int k = i >> 9, jg = i & 511, j = jg >> 2, g = jg & 3;
        g_wx0[i] = lwih0[(g * 128 + j) * 4 + k];
    }
    for (int i = i0; i < 128 * 512; i += st) {
        int k = i >> 9, jg = i & 511, j = jg >> 2, g = jg & 3;
        int row = g * 128 + j;
        g_wh0[i] = lwhh0[row * 128 + k];
        g_wi1[i] = lwih1[row * 128 + k];
        g_wh1[i] = lwhh1[row * 128 + k];
        g_wgi0[i] = (g < 3) ? gwi0[row * 128 + k] : 0.f;
        g_wgh0[i] = (g < 3) ? gwh0[row * 128 + k] : 0.f;
        g_wgi1[i] = (g < 3) ? gwi1[row * 128 + k] : 0.f;
        g_wgh1[i] = (g < 3) ? gwh1[row * 128 + k] : 0.f;
    }
    for (int i = i0; i < 512; i += st) {
        int j = i >> 2, g = i & 3;
        int row = g * 128 + j;
        g_b0[i] = lbih0[row] + lbhh0[row];
        g_b1[i] = lbih1[row] + lbhh1[row];
        g_bgi0[i] = (g < 3) ? gbi0[row] : 0.f;
        g_bgh0[i] = (g < 3) ? gbh0[row] : 0.f;
        g_bgi1[i] = (g < 3) ? gbi1[row] : 0.f;
        g_bgh1[i] = (g < 3) ? gbh1[row] : 0.f;
    }
    for (int i = i0; i < 128 * 128; i += st) {
        int k = i >> 7, j = i & 127;
        g_wbr[i] = brw[j * 128 + k];
    }
    for (int i = i0; i < 128 * 64; i += st) {
        int k = i / 64, c = i % 64;
        g_wfc1[i] = fc1w[c * 128 + k];
    }
}

__device__ __forceinline__ float sigm(float v) { return 1.f / (1.f + __expf(-v)); }

// acc[q][g] += sum_k A[r0+q][k] * W[k][j*4+g], 4 gates
__device__ __forceinline__ void mm4(const float* __restrict__ A, const float* __restrict__ W,
                                    int r0, int j4, float acc[4][4])
{
#pragma unroll 2
    for (int k = 0; k < 128; k += 4) {
        float4 w0 = *(const float4*)(W + (k + 0) * 512 + j4);
        float4 w1 = *(const float4*)(W + (k + 1) * 512 + j4);
        float4 w2 = *(const float4*)(W + (k + 2) * 512 + j4);
        float4 w3 = *(const float4*)(W + (k + 3) * 512 + j4);
#pragma unroll
        for (int q = 0; q < 4; q++) {
            float4 a = *(const float4*)(A + (r0 + q) * H + k);
            acc[q][0] = fmaf(a.x, w0.x, acc[q][0]); acc[q][1] = fmaf(a.x, w0.y, acc[q][1]);
            acc[q][2] = fmaf(a.x, w0.z, acc[q][2]); acc[q][3] = fmaf(a.x, w0.w, acc[q][3]);
            acc[q][0] = fmaf(a.y, w1.x, acc[q][0]); acc[q][1] = fmaf(a.y, w1.y, acc[q][1]);
            acc[q][2] = fmaf(a.y, w1.z, acc[q][2]); acc[q][3] = fmaf(a.y, w1.w, acc[q][3]);
            acc[q][0] = fmaf(a.z, w2.x, acc[q][0]); acc[q][1] = fmaf(a.z, w2.y, acc[q][1]);
            acc[q][2] = fmaf(a.z, w2.z, acc[q][2]); acc[q][3] = fmaf(a.z, w2.w, acc[q][3]);
            acc[q][0] = fmaf(a.w, w3.x, acc[q][0]); acc[q][1] = fmaf(a.w, w3.y, acc[q][1]);
            acc[q][2] = fmaf(a.w, w3.z, acc[q][2]); acc[q][3] = fmaf(a.w, w3.w, acc[q][3]);
        }
    }
}

// 3-gate variant (GRU): 4th weight lane ignored
__device__ __forceinline__ void mm3(const float* __restrict__ A, const float* __restrict__ W,
                                    int r0, int j4, float acc[4][3])
{
#pragma unroll 2
    for (int k = 0; k < 128; k += 4) {
        float4 w0 = *(const float4*)(W + (k + 0) * 512 + j4);
        float4 w1 = *(const float4*)(W + (k + 1) * 512 + j4);
        float4 w2 = *(const float4*)(W + (k + 2) * 512 + j4);
        float4 w3 = *(const float4*)(W + (k + 3) * 512 + j4);
#pragma unroll
        for (int q = 0; q < 4; q++) {
            float4 a = *(const float4*)(A + (r0 + q) * H + k);
            acc[q][0] = fmaf(a.x, w0.x, acc[q][0]); acc[q][1] = fmaf(a.x, w0.y, acc[q][1]);
            acc[q][2] = fmaf(a.x, w0.z, acc[q][2]);
            acc[q][0] = fmaf(a.y, w1.x, acc[q][0]); acc[q][1] = fmaf(a.y, w1.y, acc[q][1]);
            acc[q][2] = fmaf(a.y, w1.z, acc[q][2]);
            acc[q][0] = fmaf(a.z, w2.x, acc[q][0]); acc[q][1] = fmaf(a.z, w2.y, acc[q][1]);
            acc[q][2] = fmaf(a.z, w2.z, acc[q][2]);
            acc[q][0] = fmaf(a.w, w3.x, acc[q][0]); acc[q][1] = fmaf(a.w, w3.y, acc[q][1]);
            acc[q][2] = fmaf(a.w, w3.z, acc[q][2]);
        }
    }
}

__global__ void __launch_bounds__(NTHR, 1) rnn_kernel(
    const float* __restrict__ x,
    const float* __restrict__ brb, const float* __restrict__ fc1b,
    const float* __restrict__ fc2w, const float* __restrict__ fc2b,
    float* __restrict__ out)
{
    extern __shared__ float sm[];
    float* xs  = sm;              // [16][256] = all x for the tile
    float* h0b = xs + 4096;       // [2][16][128] ping-pong
    float* h1b = h0b + 4096;
    float* d0b = h1b + 4096;      // GRU hidden ping-pong
    float* d1b = d0b + 4096;
    float* fcz = d1b + 4096;      // [16][64]

    const int tid = threadIdx.x;
    const int rg = tid >> 7;         // 0..3
    const int j  = tid & 127;
    const int j4 = j * 4;
    const int r0 = rg * 4;
    const int b0 = blockIdx.x * BT;

    // preload x tile, zero initial hidden
    for (int i = tid; i < BT * 256; i += NTHR) {
        int r = i >> 8, q = i & 255;
        xs[i] = x[(size_t)(b0 + r) * 256 + q];
    }
#pragma unroll
    for (int q = 0; q < 4; q++) {
        h0b[(r0 + q) * H + j] = 0.f;
        h1b[(r0 + q) * H + j] = 0.f;
    }
    float c0r[4] = {0.f, 0.f, 0.f, 0.f};
    float c1r[4] = {0.f, 0.f, 0.f, 0.f};
    __syncthreads();

    // ---------------- LSTM encoder ----------------
    for (int t = 0; t < S; t++) {
        const int p = t & 1, np = p ^ 1;
        const float* h0p = h0b + p * 2048;
        float*       h0n = h0b + np * 2048;
        const float* h1p = h1b + p * 2048;
        float*       h1n = h1b + np * 2048;

        // layer 0: gates = x_t@wih0 + h0@whh0 + b
        {
            float acc[4][4];
            float4 bb = *(const float4*)(g_b0 + j4);
#pragma unroll
            for (int q = 0; q < 4; q++) {
                acc[q][0] = bb.x; acc[q][1] = bb.y; acc[q][2] = bb.z; acc[q][3] = bb.w;
            }
            float4 w0 = *(const float4*)(g_wx0 + 0 * 512 + j4);
            float4 w1 = *(const float4*)(g_wx0 + 1 * 512 + j4);
            float4 w2 = *(const float4*)(g_wx0 + 2 * 512 + j4);
            float4 w3 = *(const float4*)(g_wx0 + 3 * 512 + j4);
#pragma unroll
            for (int q = 0; q < 4; q++) {
                float4 a = *(const float4*)(xs + (r0 + q) * 256 + t * 4);
                acc[q][0] = fmaf(a.x, w0.x, acc[q][0]); acc[q][1] = fmaf(a.x, w0.y, acc[q][1]);
                acc[q][2] = fmaf(a.x, w0.z, acc[q][2]); acc[q][3] = fmaf(a.x, w0.w, acc[q][3]);
                acc[q][0] = fmaf(a.y, w1.x, acc[q][0]); acc[q][1] = fmaf(a.y, w1.y, acc[q][1]);
                acc[q][2] = fmaf(a.y, w1.z, acc[q][2]); acc[q][3] = fmaf(a.y, w1.w, acc[q][3]);
                acc[q][0] = fmaf(a.z, w2.x, acc[q][0]); acc[q][1] = fmaf(a.z, w2.y, acc[q][1]);
                acc[q][2] = fmaf(a.z, w2.z, acc[q][2]); acc[q][3] = fmaf(a.z, w2.w, acc[q][3]);
                acc[q][0] = fmaf(a.w, w3.x, acc[q][0]); acc[q][1] = fmaf(a.w, w3.y, acc[q][1]);
                acc[q][2] = fmaf(a.w, w3.z, acc[q][2]); acc[q][3] = fmaf(a.w, w3.w, acc[q][3]);
            }
            mm4(h0p, g_wh0, r0, j4, acc);
#pragma unroll
            for (int q = 0; q < 4; q++) {
                float cc = sigm(acc[q][1]) * c0r[q] + sigm(acc[q][0]) * tanhf(acc[q][2]);
                c0r[q] = cc;
                h0n[(r0 + q) * H + j] = sigm(acc[q][3]) * tanhf(cc);
            }
        }
        __syncthreads();

        // layer 1: gates = h0_new@wih1 + h1@whh1 + b
        {
            float acc[4][4];
            float4 bb = *(const float4*)(g_b1 + j4);
#pragma unroll
            for (int q = 0; q < 4; q++) {
                acc[q][0] = bb.x; acc[q][1] = bb.y; acc[q][2] = bb.z; acc[q][3] = bb.w;
            }
            mm4(h0n, g_wi1, r0, j4, acc);
            mm4(h1p, g_wh1, r0, j4, acc);
#pragma unroll
            for (int q = 0; q < 4; q++) {
                float cc = sigm(acc[q][1]) * c1r[q] + sigm(acc[q][0]) * tanhf(acc[q][2]);
                c1r[q] = cc;
                h1n[(r0 + q) * H + j] = sigm(acc[q][3]) * tanhf(cc);
            }
        }
        __syncthreads();
    }
    // after t=63 (p=1), final states live in buffer 0
    const float* h0f = h0b;
    const float* h1f = h1b;

    // ---------------- bridge: hd = tanh(h @ bridge^T + b) ----------------
    {
        float a0[4], a1[4];
        float bv = brb[j];
#pragma unroll
        for (int q = 0; q < 4; q++) { a0[q] = bv; a1[q] = bv; }
#pragma unroll 2
        for (int k = 0; k < 128; k += 4) {
            float w0 = g_wbr[(k + 0) * 128 + j];
            float w1 = g_wbr[(k + 1) * 128 + j];
            float w2 = g_wbr[(k + 2) * 128 + j];
            float w3 = g_wbr[(k + 3) * 128 + j];
#pragma unroll
            for (int q = 0; q < 4; q++) {
                float4 u = *(const float4*)(h0f + (r0 + q) * H + k);
                float4 v = *(const float4*)(h1f + (r0 + q) * H + k);
                a0[q] = fmaf(u.x, w0, a0[q]); a0[q] = fmaf(u.y, w1, a0[q]);
                a0[q] = fmaf(u.z, w2, a0[q]); a0[q] = fmaf(u.w, w3, a0[q]);
                a1[q] = fmaf(v.x, w0, a1[q]); a1[q] = fmaf(v.y, w1, a1[q]);
                a1[q] = fmaf(v.z, w2, a1[q]); a1[q] = fmaf(v.w, w3, a1[q]);
            }
        }
#pragma unroll
        for (int q = 0; q < 4; q++) {
            d0b[(r0 + q) * H + j] = tanhf(a0[q]);
            d1b[(r0 + q) * H + j] = tanhf(a1[q]);
        }
    }
    __syncthreads();

    // ---------------- autoregressive GRU decode + head ----------------
    for (int t = 0; t < PRED; t++) {
        const int pg = t & 1, npg = pg ^ 1;
        const float* d0p = d0b + pg * 2048;
        float*       d0n = d0b + npg * 2048;
        const float* d1p = d1b + pg * 2048;
        float*       d1n = d1b + npg * 2048;
        const float* A1 = (t == 0) ? h1f : d1p;   // dec input

        // GRU layer 0
        {
            float ai[4][3], ah[4][3];
            float4 bi = *(const float4*)(g_bgi0 + j4);
            float4 bh = *(const float4*)(g_bgh0 + j4);
#pragma unroll
            for (int q = 0; q < 4; q++) {
                ai[q][0] = bi.x; ai[q][1] = bi.y; ai[q][2] = bi.z;
                ah[q][0] = bh.x; ah[q][1] = bh.y; ah[q][2] = bh.z;
            }
            mm3(A1, g_wgi0, r0, j4, ai);
            mm3(d0p, g_wgh0, r0, j4, ah);
#pragma unroll
            for (int q = 0; q < 4; q++) {
                float hold = d0p[(r0 + q) * H + j];
                float rr = sigm(ai[q][0] + ah[q][0]);
                float zz = sigm(ai[q][1] + ah[q][1]);
                float nn = tanhf(ai[q][2] + rr * ah[q][2]);
                d0n[(r0 + q) * H + j] = (1.f - zz) * nn + zz * hold;
            }
        }
        __syncthreads();

        // GRU layer 1
        {
            float ai[4][3], ah[4][3];
            float4 bi = *(const float4*)(g_bgi1 + j4);
            float4 bh = *(const float4*)(g_bgh1 + j4);
#pragma unroll
            for (int q = 0; q < 4; q++) {
                ai[q][0] = bi.x; ai[q][1] = bi.y; ai[q][2] = bi.z;
                ah[q][0] = bh.x; ah[q][1] = bh.y; ah[q][2] = bh.z;
            }
            mm3(d0n, g_wgi1, r0, j4, ai);
            mm3(d1p, g_wgh1, r0, j4, ah);
#pragma unroll
            for (int q = 0; q < 4; q++) {
                float hold = d1p[(r0 + q) * H + j];
                float rr = sigm(ai[q][0] + ah[q][0]);
                float zz = sigm(ai[q][1] + ah[q][1]);
                float nn = tanhf(ai[q][2] + rr * ah[q][2]);
                d1n[(r0 + q) * H + j] = (1.f - zz) * nn + zz * hold;
            }
        }
        __syncthreads();

        // fc1 (relu): 1024 outputs, 2 per thread
#pragma unroll
        for (int half = 0; half < 2; half++) {
            int o = tid + half * NTHR;
            int r = o >> 6, c = o & 63;
            float acc = fc1b[c];
#pragma unroll 4
            for (int k = 0; k < 128; k += 4) {
                float4 hv = *(const float4*)(d1n + r * H + k);
                acc = fmaf(hv.x, g_wfc1[(k + 0) * 64 + c], acc);
                acc = fmaf(hv.y, g_wfc1[(k + 1) * 64 + c], acc);
                acc = fmaf(hv.z, g_wfc1[(k + 2) * 64 + c], acc);
                acc = fmaf(hv.w, g_wfc1[(k + 3) * 64 + c], acc);
            }
            fcz[r * 64 + c] = fmaxf(acc, 0.f);
        }
        __syncthreads();

        // fc2: 16 rows x 2 cols
        if (tid < 32) {
            int r = tid >> 1, cc = tid & 1;
            float s = fc2b[cc];
#pragma unroll
            for (int k = 0; k < 64; k++)
                s = fmaf(fcz[r * 64 + k], fc2w[cc * 64 + k], s);
            out[(size_t)(b0 + r) * PRED * 2 + t * 2 + cc] = s;
        }
        __syncthreads();
    }
}

extern "C" void kernel_launch(void* const* d_in, const int* in_sizes, int n_in,
                              void* d_out, int out_size)
{
    // pred_len is the only size-1 input; skip it (robust to metadata ordering).
    const float* p[24];
    int np = 0;
    for (int i = 0; i < n_in && np < 24; i++) {
        if (in_sizes[i] == 1) continue;
        p[np++] = (const float*)d_in[i];
    }
    const float* x = p[0];
    const float *lwih0 = p[1], *lwhh0 = p[2], *lbih0 = p[3], *lbhh0 = p[4];
    const float *lwih1 = p[5], *lwhh1 = p[6], *lbih1 = p[7], *lbhh1 = p[8];
    const float *gwi0 = p[9], *gwh0 = p[10], *gbi0 = p[11], *gbh0 = p[12];
    const float *gwi1 = p[13], *gwh1 = p[14], *gbi1 = p[15], *gbh1 = p[16];
    const float *brw = p[17], *brb = p[18];
    const float *fc1w = p[19], *fc1b = p[20];
    const float *fc2w = p[21], *fc2b = p[22];

    prep_kernel<<<256, 256>>>(lwih0, lwhh0, lbih0, lbhh0, lwih1, lwhh1, lbih1, lbhh1,
                              gwi0, gwh0, gbi0, gbh0, gwi1, gwh1, gbi1, gbh1,
                              brw, fc1w);

    const int smem = (4096 * 5 + 1024) * (int)sizeof(float);   // 86016 B
    cudaFuncSetAttribute(rnn_kernel, cudaFuncAttributeMaxDynamicSharedMemorySize, smem);
    rnn_kernel<<<NBLK, NTHR, smem>>>(x, brb, fc1b, fc2w, fc2b, (float*)d_out);
}